// round 5
// baseline (speedup 1.0000x reference)
#include <cuda_runtime.h>
#include <cstdint>

// ---------------------------------------------------------------------------
// SimpleSRNN: 2-layer LIF spiking RNN, B=64, T=512, D_IN=512, H1=H2=1024,
// D_OUT=256.
//   K0: transpose weights into [in][out] layout
//   K1: SGEMM  Xa[b,t,:] = x[b,t,:] @ W_in.T + b_in  (serial ascending-k FMA,
//       matching Eigen / cuBLAS accumulation grouping)
//   K2: persistent per-batch-row kernel; binary spikes -> sparse row sums in
//       ASCENDING index order from a zero-initialized accumulator, composed
//       exactly as the reference:  ((xW+b_in) + R1) + b_h1  etc.
// ---------------------------------------------------------------------------

#define BETA 0.9f
#define THRESH 1.0f

static constexpr int B = 64;
static constexpr int T = 512;
static constexpr int DIN = 512;
static constexpr int H = 1024;      // H1 == H2
static constexpr int DOUT = 256;

// ---- device scratch (static allocation only) ------------------------------
__device__ float g_Xa[(size_t)B * T * H];      // x@W_in.T + b_in  (128 MB)
__device__ float g_WT_h1[H * H];               // [j][i] = W_h1[i][j]
__device__ float g_WT_12[H * H];
__device__ float g_WT_h2[H * H];
__device__ float g_WT_in[DIN * H];             // [k][i]
__device__ float g_WT_out[H * DOUT];           // [j][o]

// ---------------------------------------------------------------------------
// K0: weight transposes
// ---------------------------------------------------------------------------
__global__ void prep_kernel(const float* __restrict__ W_in,
                            const float* __restrict__ W_h1,
                            const float* __restrict__ W_12,
                            const float* __restrict__ W_h2,
                            const float* __restrict__ W_out) {
    const int stride = gridDim.x * blockDim.x;
    const int g = blockIdx.x * blockDim.x + threadIdx.x;

    for (int d = g; d < DIN * H; d += stride) {
        int k = d >> 10, i = d & (H - 1);
        g_WT_in[d] = W_in[i * DIN + k];
    }
    for (int d = g; d < H * H; d += stride) {
        int j = d >> 10, i = d & (H - 1);
        g_WT_h1[d] = W_h1[i * H + j];
    }
    for (int d = g; d < H * H; d += stride) {
        int j = d >> 10, i = d & (H - 1);
        g_WT_12[d] = W_12[i * H + j];
    }
    for (int d = g; d < H * H; d += stride) {
        int j = d >> 10, i = d & (H - 1);
        g_WT_h2[d] = W_h2[i * H + j];
    }
    for (int d = g; d < H * DOUT; d += stride) {
        int j = d >> 8, o = d & (DOUT - 1);
        g_WT_out[d] = W_out[o * H + j];
    }
}

// ---------------------------------------------------------------------------
// K1: SGEMM  g_Xa = x @ g_WT_in + b_in
//     M = B*T = 32768, K = 512, N = 1024.
//     Per output element: single accumulator, ascending-k FMA chain.
// ---------------------------------------------------------------------------
#define GM (B * T)
#define GN H
#define GK DIN
#define BMT 128
#define BNT 64
#define BKT 16

__global__ __launch_bounds__(256) void gemm_xa(const float* __restrict__ x,
                                               const float* __restrict__ b_in) {
    __shared__ float As[2][BKT][BMT + 4];
    __shared__ float Bs[2][BKT][BNT];

    const int bm = blockIdx.y * BMT;
    const int bn = blockIdx.x * BNT;
    const int tid = threadIdx.x;
    const int tx = tid & 15;   // n
    const int ty = tid >> 4;   // m

    float acc[8][4];
#pragma unroll
    for (int i = 0; i < 8; ++i)
#pragma unroll
        for (int j = 0; j < 4; ++j) acc[i][j] = 0.0f;

    const int a_row0 = tid >> 2;
    const int a_kc = (tid & 3) * 4;
    const int b_k = tid >> 4;
    const int b_c = (tid & 15) * 4;

    const float* Aptr = x + (size_t)(bm + a_row0) * GK + a_kc;
    const float* Bptr = g_WT_in + (size_t)b_k * GN + bn + b_c;

    float4 pa0 = *(const float4*)(Aptr);
    float4 pa1 = *(const float4*)(Aptr + 64 * GK);
    float4 pb = *(const float4*)(Bptr);

    As[0][a_kc + 0][a_row0] = pa0.x;
    As[0][a_kc + 1][a_row0] = pa0.y;
    As[0][a_kc + 2][a_row0] = pa0.z;
    As[0][a_kc + 3][a_row0] = pa0.w;
    As[0][a_kc + 0][a_row0 + 64] = pa1.x;
    As[0][a_kc + 1][a_row0 + 64] = pa1.y;
    As[0][a_kc + 2][a_row0 + 64] = pa1.z;
    As[0][a_kc + 3][a_row0 + 64] = pa1.w;
    *(float4*)&Bs[0][b_k][b_c] = pb;
    __syncthreads();

    const int KT = GK / BKT;
    int buf = 0;
    for (int kt = 0; kt < KT; ++kt) {
        if (kt + 1 < KT) {
            const float* Ap = Aptr + (kt + 1) * BKT;
            pa0 = *(const float4*)(Ap);
            pa1 = *(const float4*)(Ap + 64 * GK);
            pb = *(const float4*)(Bptr + (size_t)(kt + 1) * BKT * GN);
        }
#pragma unroll
        for (int k = 0; k < BKT; ++k) {
            float4 a0 = *(const float4*)&As[buf][k][ty * 8];
            float4 a1 = *(const float4*)&As[buf][k][ty * 8 + 4];
            float4 bb = *(const float4*)&Bs[buf][k][tx * 4];
            float am[8] = {a0.x, a0.y, a0.z, a0.w, a1.x, a1.y, a1.z, a1.w};
            float bv[4] = {bb.x, bb.y, bb.z, bb.w};
#pragma unroll
            for (int i = 0; i < 8; ++i)
#pragma unroll
                for (int j = 0; j < 4; ++j)
                    acc[i][j] = fmaf(am[i], bv[j], acc[i][j]);
        }
        if (kt + 1 < KT) {
            const int nb = buf ^ 1;
            As[nb][a_kc + 0][a_row0] = pa0.x;
            As[nb][a_kc + 1][a_row0] = pa0.y;
            As[nb][a_kc + 2][a_row0] = pa0.z;
            As[nb][a_kc + 3][a_row0] = pa0.w;
            As[nb][a_kc + 0][a_row0 + 64] = pa1.x;
            As[nb][a_kc + 1][a_row0 + 64] = pa1.y;
            As[nb][a_kc + 2][a_row0 + 64] = pa1.z;
            As[nb][a_kc + 3][a_row0 + 64] = pa1.w;
            *(float4*)&Bs[nb][b_k][b_c] = pb;
        }
        buf ^= 1;
        __syncthreads();
    }

    float bias[4];
#pragma unroll
    for (int j = 0; j < 4; ++j) bias[j] = b_in[bn + tx * 4 + j];
#pragma unroll
    for (int i = 0; i < 8; ++i) {
        float4 o;
        o.x = acc[i][0] + bias[0];
        o.y = acc[i][1] + bias[1];
        o.z = acc[i][2] + bias[2];
        o.w = acc[i][3] + bias[3];
        *(float4*)&g_Xa[(size_t)(bm + ty * 8 + i) * GN + bn + tx * 4] = o;
    }
}

// ---------------------------------------------------------------------------
// K2: persistent recurrent kernel, 64 CTAs x 256 threads.
// ---------------------------------------------------------------------------
__device__ __forceinline__ unsigned long long addx2(unsigned long long a,
                                                    unsigned long long b) {
    unsigned long long r;
    asm("add.rn.f32x2 %0, %1, %2;" : "=l"(r) : "l"(a), "l"(b));
    return r;
}
__device__ __forceinline__ float lo2(unsigned long long v) {
    return __int_as_float((int)(unsigned)(v & 0xffffffffull));
}
__device__ __forceinline__ float hi2(unsigned long long v) {
    return __int_as_float((int)(unsigned)(v >> 32));
}

__global__ __launch_bounds__(256, 1) void srnn_kernel(const float* __restrict__ b_h1,
                                                      const float* __restrict__ b_12,
                                                      const float* __restrict__ b_h2,
                                                      const float* __restrict__ b_out,
                                                      float* __restrict__ out) {
    const int b = blockIdx.x;
    const int tid = threadIdx.x;
    const int lane = tid & 31;

    __shared__ unsigned short idx1[H];
    __shared__ unsigned short idx2[H];
    __shared__ unsigned int nibs[256];   // 4-bit spike mask per thread
    __shared__ int cnt_s;
    __shared__ float4 red4[256];

    const int col = tid * 4;
    const float* wh1 = g_WT_h1 + col;
    const float* w12 = g_WT_12 + col;
    const float* wh2 = g_WT_h2 + col;

    float4 v1 = make_float4(0.f, 0.f, 0.f, 0.f);
    float4 v2 = make_float4(0.f, 0.f, 0.f, 0.f);

    const float4 bh1 = *(const float4*)(b_h1 + col);
    const float4 b12 = *(const float4*)(b_12 + col);
    const float4 bh2 = *(const float4*)(b_h2 + col);

    // readout: 4 interleaved partial accumulators per output quad
    const int r = tid >> 6;       // 0..3
    const int o = tid & 63;       // output quad id
    const float* wout = g_WT_out + o * 4;
    float4 accp = make_float4(0.f, 0.f, 0.f, 0.f);
    float4 bo = make_float4(0.f, 0.f, 0.f, 0.f);
    if (r == 0) bo = *(const float4*)(b_out + o * 4);

    const float* Xb = g_Xa + (size_t)b * T * H;

    int cnt1 = 0, cnt2 = 0;

    for (int t = 0; t < T; ++t) {
        // ================= layer 1 =================
        // R1 = s1_prev @ W_h1.T  — standalone ascending-j sum from zero
        unsigned long long r01 = 0ull, r23 = 0ull;
#pragma unroll 4
        for (int k = 0; k < cnt1; ++k) {
            ulonglong2 w = *(const ulonglong2*)(const void*)(wh1 + ((int)idx1[k] << 10));
            r01 = addx2(r01, w.x);
            r23 = addx2(r23, w.y);
        }
        float4 hx = *(const float4*)(Xb + t * H + col);   // xW + b_in
        // h1 = ((xW + b_in) + R1) + b_h1   (reference grouping)
        float n0 = (hx.x + lo2(r01)) + bh1.x;
        float n1 = (hx.y + hi2(r01)) + bh1.y;
        float n2 = (hx.z + lo2(r23)) + bh1.z;
        float n3 = (hx.w + hi2(r23)) + bh1.w;
        v1.x = fmaf(BETA, v1.x, n0);
        v1.y = fmaf(BETA, v1.y, n1);
        v1.z = fmaf(BETA, v1.z, n2);
        v1.w = fmaf(BETA, v1.w, n3);
        bool s0 = v1.x >= THRESH;
        bool s1 = v1.y >= THRESH;
        bool s2 = v1.z >= THRESH;
        bool s3 = v1.w >= THRESH;
        if (s0) v1.x -= THRESH;
        if (s1) v1.y -= THRESH;
        if (s2) v1.z -= THRESH;
        if (s3) v1.w -= THRESH;
        nibs[tid] = (unsigned)s0 | ((unsigned)s1 << 1) | ((unsigned)s2 << 2) |
                    ((unsigned)s3 << 3);
        __syncthreads();
        if (tid < 32) {   // compact: ascending global column order
            const unsigned int* nb = &nibs[tid * 8];
            unsigned m = 0;
#pragma unroll
            for (int i = 0; i < 8; ++i) m |= nb[i] << (i * 4);
            int p = __popc(m);
            int off = p;
#pragma unroll
            for (int s = 1; s < 32; s <<= 1) {
                int n = __shfl_up_sync(0xffffffffu, off, s);
                if (lane >= s) off += n;
            }
            if (tid == 31) cnt_s = off;
            off -= p;
            const int base = tid * 32;
            while (m) {
                int bit = __ffs(m) - 1;
                m &= m - 1;
                idx1[off++] = (unsigned short)(base + bit);
            }
        }
        __syncthreads();
        cnt1 = cnt_s;

        // ================= layer 2 =================
        // R12 = s1_new @ W_12.T ; R22 = s2_prev @ W_h2.T  — separate sums
        unsigned long long a01 = 0ull, a23 = 0ull;
#pragma unroll 4
        for (int k = 0; k < cnt1; ++k) {
            ulonglong2 w = *(const ulonglong2*)(const void*)(w12 + ((int)idx1[k] << 10));
            a01 = addx2(a01, w.x);
            a23 = addx2(a23, w.y);
        }
        unsigned long long c01 = 0ull, c23 = 0ull;
#pragma unroll 4
        for (int k = 0; k < cnt2; ++k) {
            ulonglong2 w = *(const ulonglong2*)(const void*)(wh2 + ((int)idx2[k] << 10));
            c01 = addx2(c01, w.x);
            c23 = addx2(c23, w.y);
        }
        __syncthreads();   // idx2 about to be overwritten
        // h2 = ((R12 + b_12) + R22) + b_h2   (reference grouping)
        float m0 = ((lo2(a01) + b12.x) + lo2(c01)) + bh2.x;
        float m1 = ((hi2(a01) + b12.y) + hi2(c01)) + bh2.y;
        float m2 = ((lo2(a23) + b12.z) + lo2(c23)) + bh2.z;
        float m3 = ((hi2(a23) + b12.w) + hi2(c23)) + bh2.w;
        v2.x = fmaf(BETA, v2.x, m0);
        v2.y = fmaf(BETA, v2.y, m1);
        v2.z = fmaf(BETA, v2.z, m2);
        v2.w = fmaf(BETA, v2.w, m3);
        s0 = v2.x >= THRESH;
        s1 = v2.y >= THRESH;
        s2 = v2.z >= THRESH;
        s3 = v2.w >= THRESH;
        if (s0) v2.x -= THRESH;
        if (s1) v2.y -= THRESH;
        if (s2) v2.z -= THRESH;
        if (s3) v2.w -= THRESH;
        nibs[tid] = (unsigned)s0 | ((unsigned)s1 << 1) | ((unsigned)s2 << 2) |
                    ((unsigned)s3 << 3);
        __syncthreads();
        if (tid < 32) {
            const unsigned int* nb = &nibs[tid * 8];
            unsigned m = 0;
#pragma unroll
            for (int i = 0; i < 8; ++i) m |= nb[i] << (i * 4);
            int p = __popc(m);
            int off = p;
#pragma unroll
            for (int s = 1; s < 32; s <<= 1) {
                int n = __shfl_up_sync(0xffffffffu, off, s);
                if (lane >= s) off += n;
            }
            if (tid == 31) cnt_s = off;
            off -= p;
            const int base = tid * 32;
            while (m) {
                int bit = __ffs(m) - 1;
                m &= m - 1;
                idx2[off++] = (unsigned short)(base + bit);
            }
        }
        __syncthreads();
        cnt2 = cnt_s;

        // ================= readout acc (order-noise only, no feedback) =====
        {
            float4 a = accp;
            if (r == 0) {
                a.x += bo.x;
                a.y += bo.y;
                a.z += bo.z;
                a.w += bo.w;
            }
#pragma unroll 2
            for (int k = r; k < cnt2; k += 4) {
                float4 w = *(const float4*)(wout + ((int)idx2[k] << 8));
                a.x += w.x;
                a.y += w.y;
                a.z += w.z;
                a.w += w.w;
            }
            accp = a;
        }
    }

    // final deterministic reduction of the 4 readout partials
    red4[tid] = accp;
    __syncthreads();
    if (tid < 64) {
        float4 s = red4[tid];
        float4 p1 = red4[tid + 64];
        float4 p2 = red4[tid + 128];
        float4 p3 = red4[tid + 192];
        s.x += p1.x; s.y += p1.y; s.z += p1.z; s.w += p1.w;
        s.x += p2.x; s.y += p2.y; s.z += p2.z; s.w += p2.w;
        s.x += p3.x; s.y += p3.y; s.z += p3.z; s.w += p3.w;
        *(float4*)&out[b * DOUT + tid * 4] = s;
    }
}

// ---------------------------------------------------------------------------
// kernel_launch
// Inputs: 0 x, 1 W_in, 2 b_in, 3 W_h1, 4 b_h1, 5 W_12, 6 b_12, 7 W_h2,
//         8 b_h2, 9 W_out, 10 b_out
// ---------------------------------------------------------------------------
extern "C" void kernel_launch(void* const* d_in, const int* in_sizes, int n_in,
                              void* d_out, int out_size) {
    const float* x = (const float*)d_in[0];
    const float* W_in = (const float*)d_in[1];
    const float* b_in = (const float*)d_in[2];
    const float* W_h1 = (const float*)d_in[3];
    const float* b_h1 = (const float*)d_in[4];
    const float* W_12 = (const float*)d_in[5];
    const float* b_12 = (const float*)d_in[6];
    const float* W_h2 = (const float*)d_in[7];
    const float* b_h2 = (const float*)d_in[8];
    const float* W_out = (const float*)d_in[9];
    const float* b_out = (const float*)d_in[10];
    float* out = (float*)d_out;

    prep_kernel<<<1024, 256>>>(W_in, W_h1, W_12, W_h2, W_out);
    gemm_xa<<<dim3(GN / BNT, GM / BMT, 1), 256>>>(x, b_in);
    srnn_kernel<<<B, 256>>>(b_h1, b_12, b_h2, b_out, out);
}

// round 7
// speedup vs baseline: 1.0020x; 1.0020x over previous
#include <cuda_runtime.h>
#include <cstdint>

// ---------------------------------------------------------------------------
// SimpleSRNN: 2-layer LIF spiking RNN, B=64, T=512, D_IN=512, H1=H2=1024,
// D_OUT=256.
//   K0: transpose weights + zero progress flags
//   K_fused: CTAs 0..63   = persistent per-batch recurrent consumers
//            CTAs 64..4159 = SGEMM producer tiles (Xa = x@W_in.T + b_in)
//   Producer/consumer coupling via per-(batch, t-block) arrival counters:
//   srnn CTA b waits until all 16 N-tiles of its next 128-step block of Xa
//   have been stored (threadfence + atomicAdd release / spin + fence acquire).
//   All arithmetic (grouping, order) identical to the passing Round-5 kernel.
// ---------------------------------------------------------------------------

#define BETA 0.9f
#define THRESH 1.0f

static constexpr int B = 64;
static constexpr int T = 512;
static constexpr int DIN = 512;
static constexpr int H = 1024;      // H1 == H2
static constexpr int DOUT = 256;

// ---- device scratch (static allocation only) ------------------------------
__device__ float g_Xa[(size_t)B * T * H];      // x@W_in.T + b_in  (128 MB)
__device__ float g_WT_h1[H * H];               // [j][i] = W_h1[i][j]
__device__ float g_WT_12[H * H];
__device__ float g_WT_h2[H * H];
__device__ float g_WT_in[DIN * H];             // [k][i]
__device__ float g_WT_out[H * DOUT];           // [j][o]
__device__ int   g_flag[B][4];                 // tiles done per (batch, tblock)

// ---------------------------------------------------------------------------
// K0: weight transposes + flag reset (reset needed on every graph replay)
// ---------------------------------------------------------------------------
__global__ void prep_kernel(const float* __restrict__ W_in,
                            const float* __restrict__ W_h1,
                            const float* __restrict__ W_12,
                            const float* __restrict__ W_h2,
                            const float* __restrict__ W_out) {
    const int stride = gridDim.x * blockDim.x;
    const int g = blockIdx.x * blockDim.x + threadIdx.x;

    if (g < B * 4) ((int*)g_flag)[g] = 0;

    for (int d = g; d < DIN * H; d += stride) {
        int k = d >> 10, i = d & (H - 1);
        g_WT_in[d] = W_in[i * DIN + k];
    }
    for (int d = g; d < H * H; d += stride) {
        int j = d >> 10, i = d & (H - 1);
        g_WT_h1[d] = W_h1[i * H + j];
    }
    for (int d = g; d < H * H; d += stride) {
        int j = d >> 10, i = d & (H - 1);
        g_WT_12[d] = W_12[i * H + j];
    }
    for (int d = g; d < H * H; d += stride) {
        int j = d >> 10, i = d & (H - 1);
        g_WT_h2[d] = W_h2[i * H + j];
    }
    for (int d = g; d < H * DOUT; d += stride) {
        int j = d >> 8, o = d & (DOUT - 1);
        g_WT_out[d] = W_out[o * H + j];
    }
}

// ---------------------------------------------------------------------------
// GEMM body: Xa tile (128 rows of one batch's t-block) x (64 cols).
// Per element: single accumulator, ascending-k FMA chain (bit-exact vs R5).
// ---------------------------------------------------------------------------
#define GN H
#define GK DIN
#define BMT 128
#define BNT 64
#define BKT 16
#define NTILES (GN / BNT)   // 16

__device__ void gemm_body(const float* __restrict__ x,
                          const float* __restrict__ b_in, int gidx) {
    __shared__ float As[2][BKT][BMT + 4];
    __shared__ float Bs[2][BKT][BNT];

    const int bx = gidx & (NTILES - 1);
    const int byr = gidx >> 4;           // 0..255
    const int tb = byr >> 6;             // t-block 0..3  (t-block major order)
    const int bb = byr & 63;             // batch
    const int bm = bb * T + tb * BMT;    // global M row base
    const int bn = bx * BNT;
    const int tid = threadIdx.x;
    const int tx = tid & 15;   // n
    const int ty = tid >> 4;   // m

    float acc[8][4];
#pragma unroll
    for (int i = 0; i < 8; ++i)
#pragma unroll
        for (int j = 0; j < 4; ++j) acc[i][j] = 0.0f;

    const int a_row0 = tid >> 2;
    const int a_kc = (tid & 3) * 4;
    const int b_k = tid >> 4;
    const int b_c = (tid & 15) * 4;

    const float* Aptr = x + (size_t)(bm + a_row0) * GK + a_kc;
    const float* Bptr = g_WT_in + (size_t)b_k * GN + bn + b_c;

    float4 pa0 = *(const float4*)(Aptr);
    float4 pa1 = *(const float4*)(Aptr + 64 * GK);
    float4 pb = *(const float4*)(Bptr);

    As[0][a_kc + 0][a_row0] = pa0.x;
    As[0][a_kc + 1][a_row0] = pa0.y;
    As[0][a_kc + 2][a_row0] = pa0.z;
    As[0][a_kc + 3][a_row0] = pa0.w;
    As[0][a_kc + 0][a_row0 + 64] = pa1.x;
    As[0][a_kc + 1][a_row0 + 64] = pa1.y;
    As[0][a_kc + 2][a_row0 + 64] = pa1.z;
    As[0][a_kc + 3][a_row0 + 64] = pa1.w;
    *(float4*)&Bs[0][b_k][b_c] = pb;
    __syncthreads();

    const int KT = GK / BKT;
    int buf = 0;
    for (int kt = 0; kt < KT; ++kt) {
        if (kt + 1 < KT) {
            const float* Ap = Aptr + (kt + 1) * BKT;
            pa0 = *(const float4*)(Ap);
            pa1 = *(const float4*)(Ap + 64 * GK);
            pb = *(const float4*)(Bptr + (size_t)(kt + 1) * BKT * GN);
        }
#pragma unroll
        for (int k = 0; k < BKT; ++k) {
            float4 a0 = *(const float4*)&As[buf][k][ty * 8];
            float4 a1 = *(const float4*)&As[buf][k][ty * 8 + 4];
            float4 bb2 = *(const float4*)&Bs[buf][k][tx * 4];
            float am[8] = {a0.x, a0.y, a0.z, a0.w, a1.x, a1.y, a1.z, a1.w};
            float bv[4] = {bb2.x, bb2.y, bb2.z, bb2.w};
#pragma unroll
            for (int i = 0; i < 8; ++i)
#pragma unroll
                for (int j = 0; j < 4; ++j)
                    acc[i][j] = fmaf(am[i], bv[j], acc[i][j]);
        }
        if (kt + 1 < KT) {
            const int nb = buf ^ 1;
            As[nb][a_kc + 0][a_row0] = pa0.x;
            As[nb][a_kc + 1][a_row0] = pa0.y;
            As[nb][a_kc + 2][a_row0] = pa0.z;
            As[nb][a_kc + 3][a_row0] = pa0.w;
            As[nb][a_kc + 0][a_row0 + 64] = pa1.x;
            As[nb][a_kc + 1][a_row0 + 64] = pa1.y;
            As[nb][a_kc + 2][a_row0 + 64] = pa1.z;
            As[nb][a_kc + 3][a_row0 + 64] = pa1.w;
            *(float4*)&Bs[nb][b_k][b_c] = pb;
        }
        buf ^= 1;
        __syncthreads();
    }

    float bias[4];
#pragma unroll
    for (int j = 0; j < 4; ++j) bias[j] = b_in[bn + tx * 4 + j];
#pragma unroll
    for (int i = 0; i < 8; ++i) {
        float4 o;
        o.x = acc[i][0] + bias[0];
        o.y = acc[i][1] + bias[1];
        o.z = acc[i][2] + bias[2];
        o.w = acc[i][3] + bias[3];
        *(float4*)&g_Xa[(size_t)(bm + ty * 8 + i) * GN + bn + tx * 4] = o;
    }

    // release: all this CTA's stores visible before the arrival is counted
    __threadfence();
    __syncthreads();
    if (tid == 0) atomicAdd(&g_flag[bb][tb], 1);
}

// ---------------------------------------------------------------------------
// srnn body (identical math to Round-5), plus a producer wait every 128 steps.
// ---------------------------------------------------------------------------
__device__ __forceinline__ unsigned long long addx2(unsigned long long a,
                                                    unsigned long long b) {
    unsigned long long r;
    asm("add.rn.f32x2 %0, %1, %2;" : "=l"(r) : "l"(a), "l"(b));
    return r;
}
__device__ __forceinline__ float lo2(unsigned long long v) {
    return __int_as_float((int)(unsigned)(v & 0xffffffffull));
}
__device__ __forceinline__ float hi2(unsigned long long v) {
    return __int_as_float((int)(unsigned)(v >> 32));
}

__device__ void srnn_body(const float* __restrict__ b_h1,
                          const float* __restrict__ b_12,
                          const float* __restrict__ b_h2,
                          const float* __restrict__ b_out,
                          float* __restrict__ out) {
    const int b = blockIdx.x;
    const int tid = threadIdx.x;
    const int lane = tid & 31;

    __shared__ unsigned short idx1[H];
    __shared__ unsigned short idx2[H];
    __shared__ unsigned int nibs[256];
    __shared__ int cnt_s;
    __shared__ float4 red4[256];

    const int col = tid * 4;
    const float* wh1 = g_WT_h1 + col;
    const float* w12 = g_WT_12 + col;
    const float* wh2 = g_WT_h2 + col;

    float4 v1 = make_float4(0.f, 0.f, 0.f, 0.f);
    float4 v2 = make_float4(0.f, 0.f, 0.f, 0.f);

    const float4 bh1 = *(const float4*)(b_h1 + col);
    const float4 b12 = *(const float4*)(b_12 + col);
    const float4 bh2 = *(const float4*)(b_h2 + col);

    const int r = tid >> 6;
    const int o = tid & 63;
    const float* wout = g_WT_out + o * 4;
    float4 accp = make_float4(0.f, 0.f, 0.f, 0.f);
    float4 bo = make_float4(0.f, 0.f, 0.f, 0.f);
    if (r == 0) bo = *(const float4*)(b_out + o * 4);

    const float* Xb = g_Xa + (size_t)b * T * H;

    int cnt1 = 0, cnt2 = 0;

    for (int t = 0; t < T; ++t) {
        if ((t & 127) == 0) {          // acquire next 128-step block of Xa
            const int tb = t >> 7;
            if (tid == 0) {
                while (atomicAdd(&g_flag[b][tb], 0) < NTILES) __nanosleep(200);
            }
            __syncthreads();
            __threadfence();
        }

        // ================= layer 1 =================
        unsigned long long r01 = 0ull, r23 = 0ull;
#pragma unroll 4
        for (int k = 0; k < cnt1; ++k) {
            ulonglong2 w = *(const ulonglong2*)(const void*)(wh1 + ((int)idx1[k] << 10));
            r01 = addx2(r01, w.x);
            r23 = addx2(r23, w.y);
        }
        float4 hx = *(const float4*)(Xb + t * H + col);
        float n0 = (hx.x + lo2(r01)) + bh1.x;
        float n1 = (hx.y + hi2(r01)) + bh1.y;
        float n2 = (hx.z + lo2(r23)) + bh1.z;
        float n3 = (hx.w + hi2(r23)) + bh1.w;
        v1.x = fmaf(BETA, v1.x, n0);
        v1.y = fmaf(BETA, v1.y, n1);
        v1.z = fmaf(BETA, v1.z, n2);
        v1.w = fmaf(BETA, v1.w, n3);
        bool s0 = v1.x >= THRESH;
        bool s1 = v1.y >= THRESH;
        bool s2 = v1.z >= THRESH;
        bool s3 = v1.w >= THRESH;
        if (s0) v1.x -= THRESH;
        if (s1) v1.y -= THRESH;
        if (s2) v1.z -= THRESH;
        if (s3) v1.w -= THRESH;
        nibs[tid] = (unsigned)s0 | ((unsigned)s1 << 1) | ((unsigned)s2 << 2) |
                    ((unsigned)s3 << 3);
        __syncthreads();
        if (tid < 32) {
            const unsigned int* nb = &nibs[tid * 8];
            unsigned m = 0;
#pragma unroll
            for (int i = 0; i < 8; ++i) m |= nb[i] << (i * 4);
            int p = __popc(m);
            int off = p;
#pragma unroll
            for (int s = 1; s < 32; s <<= 1) {
                int n = __shfl_up_sync(0xffffffffu, off, s);
                if (lane >= s) off += n;
            }
            if (tid == 31) cnt_s = off;
            off -= p;
            const int base = tid * 32;
            while (m) {
                int bit = __ffs(m) - 1;
                m &= m - 1;
                idx1[off++] = (unsigned short)(base + bit);
            }
        }
        __syncthreads();
        cnt1 = cnt_s;

        // ================= layer 2 =================
        unsigned long long a01 = 0ull, a23 = 0ull;
#pragma unroll 4
        for (int k = 0; k < cnt1; ++k) {
            ulonglong2 w = *(const ulonglong2*)(const void*)(w12 + ((int)idx1[k] << 10));
            a01 = addx2(a01, w.x);
            a23 = addx2(a23, w.y);
        }
        unsigned long long c01 = 0ull, c23 = 0ull;
#pragma unroll 4
        for (int k = 0; k < cnt2; ++k) {
            ulonglong2 w = *(const ulonglong2*)(const void*)(wh2 + ((int)idx2[k] << 10));
            c01 = addx2(c01, w.x);
            c23 = addx2(c23, w.y);
        }
        __syncthreads();   // idx2 about to be overwritten
        float m0 = ((lo2(a01) + b12.x) + lo2(c01)) + bh2.x;
        float m1 = ((hi2(a01) + b12.y) + hi2(c01)) + bh2.y;
        float m2 = ((lo2(a23) + b12.z) + lo2(c23)) + bh2.z;
        float m3 = ((hi2(a23) + b12.w) + hi2(c23)) + bh2.w;
        v2.x = fmaf(BETA, v2.x, m0);
        v2.y = fmaf(BETA, v2.y, m1);
        v2.z = fmaf(BETA, v2.z, m2);
        v2.w = fmaf(BETA, v2.w, m3);
        s0 = v2.x >= THRESH;
        s1 = v2.y >= THRESH;
        s2 = v2.z >= THRESH;
        s3 = v2.w >= THRESH;
        if (s0) v2.x -= THRESH;
        if (s1) v2.y -= THRESH;
        if (s2) v2.z -= THRESH;
        if (s3) v2.w -= THRESH;
        nibs[tid] = (unsigned)s0 | ((unsigned)s1 << 1) | ((unsigned)s2 << 2) |
                    ((unsigned)s3 << 3);
        __syncthreads();
        if (tid < 32) {
            const unsigned int* nb = &nibs[tid * 8];
            unsigned m = 0;
#pragma unroll
            for (int i = 0; i < 8; ++i) m |= nb[i] << (i * 4);
            int p = __popc(m);
            int off = p;
#pragma unroll
            for (int s = 1; s < 32; s <<= 1) {
                int n = __shfl_up_sync(0xffffffffu, off, s);
                if (lane >= s) off += n;
            }
            if (tid == 31) cnt_s = off;
            off -= p;
            const int base = tid * 32;
            while (m) {
                int bit = __ffs(m) - 1;
                m &= m - 1;
                idx2[off++] = (unsigned short)(base + bit);
            }
        }
        __syncthreads();
        cnt2 = cnt_s;

        // ================= readout acc =================
        {
            float4 a = accp;
            if (r == 0) {
                a.x += bo.x;
                a.y += bo.y;
                a.z += bo.z;
                a.w += bo.w;
            }
#pragma unroll 2
            for (int k = r; k < cnt2; k += 4) {
                float4 w = *(const float4*)(wout + ((int)idx2[k] << 8));
                a.x += w.x;
                a.y += w.y;
                a.z += w.z;
                a.w += w.w;
            }
            accp = a;
        }
    }

    red4[tid] = accp;
    __syncthreads();
    if (tid < 64) {
        float4 s = red4[tid];
        float4 p1 = red4[tid + 64];
        float4 p2 = red4[tid + 128];
        float4 p3 = red4[tid + 192];
        s.x += p1.x; s.y += p1.y; s.z += p1.z; s.w += p1.w;
        s.x += p2.x; s.y += p2.y; s.z += p2.z; s.w += p2.w;
        s.x += p3.x; s.y += p3.y; s.z += p3.z; s.w += p3.w;
        *(float4*)&out[b * DOUT + tid * 4] = s;
    }
}

// ---------------------------------------------------------------------------
// Fused producer/consumer kernel.
// CTAs 0..63: srnn consumers (wave-1 resident on distinct SMs).
// CTAs 64..4159: gemm producer tiles, t-block-major so early blocks land first.
// ---------------------------------------------------------------------------
__global__ __launch_bounds__(256, 2) void fused_kernel(
    const float* __restrict__ x, const float* __restrict__ b_in,
    const float* __restrict__ b_h1, const float* __restrict__ b_12,
    const float* __restrict__ b_h2, const float* __restrict__ b_out,
    float* __restrict__ out) {
    if (blockIdx.x < B) {
        srnn_body(b_h1, b_12, b_h2, b_out, out);
    } else {
        gemm_body(x, b_in, blockIdx.x - B);
    }
}

// ---------------------------------------------------------------------------
// kernel_launch
// Inputs: 0 x, 1 W_in, 2 b_in, 3 W_h1, 4 b_h1, 5 W_12, 6 b_12, 7 W_h2,
//         8 b_h2, 9 W_out, 10 b_out
// ---------------------------------------------------------------------------
extern "C" void kernel_launch(void* const* d_in, const int* in_sizes, int n_in,
                              void* d_out, int out_size) {
    const float* x = (const float*)d_in[0];
    const float* W_in = (const float*)d_in[1];
    const float* b_in = (const float*)d_in[2];
    const float* W_h1 = (const float*)d_in[3];
    const float* b_h1 = (const float*)d_in[4];
    const float* W_12 = (const float*)d_in[5];
    const float* b_12 = (const float*)d_in[6];
    const float* W_h2 = (const float*)d_in[7];
    const float* b_h2 = (const float*)d_in[8];
    const float* W_out = (const float*)d_in[9];
    const float* b_out = (const float*)d_in[10];
    float* out = (float*)d_out;

    prep_kernel<<<1024, 256>>>(W_in, W_h1, W_12, W_h2, W_out);
    const int total_tiles = (B * T / BMT) * NTILES;   // 4096
    fused_kernel<<<B + total_tiles, 256>>>(x, b_in, b_h1, b_12, b_h2, b_out, out);
}

// round 11
// speedup vs baseline: 1.6821x; 1.6788x over previous
#include <cuda_runtime.h>
#include <cstdint>

// ---------------------------------------------------------------------------
// SimpleSRNN: 2-layer LIF spiking RNN, B=64, T=512, D_IN=512, H1=H2=1024,
// D_OUT=256.
//   K0: transpose weights (+ zero pad-row) + zero progress flags
//   K_fused: CTAs 0..63 = persistent per-batch recurrent consumers,
//            CTAs 64..4159 = SGEMM producer tiles (Xa = x@W_in.T + b_in).
//   R7 -> R8: spike-row accumulation is software-pipelined with 2x8-row
//   register buffers (MLP ~16 vs ~4). Index lists padded to multiples of 16
//   with a ZERO weight row (exact: x + 0.0 == x), preserving the bit-exact
//   accumulation order of the passing kernel.
// ---------------------------------------------------------------------------

#define BETA 0.9f
#define THRESH 1.0f

static constexpr int B = 64;
static constexpr int T = 512;
static constexpr int DIN = 512;
static constexpr int H = 1024;      // H1 == H2
static constexpr int DOUT = 256;
static constexpr int ZROW = H;      // index of the all-zero pad row

// ---- device scratch (static allocation only) ------------------------------
__device__ float g_Xa[(size_t)B * T * H];          // x@W_in.T + b_in (128 MB)
__device__ float g_WT_h1[H * H + H];               // [j][i], + zero row
__device__ float g_WT_12[H * H + H];
__device__ float g_WT_h2[H * H + H];
__device__ float g_WT_in[DIN * H];                 // [k][i]
__device__ float g_WT_out[H * DOUT + DOUT];        // [j][o], + zero row
__device__ int   g_flag[B][4];                     // tiles done per (b, tblock)

// ---------------------------------------------------------------------------
// K0: weight transposes + zero rows + flag reset
// ---------------------------------------------------------------------------
__global__ void prep_kernel(const float* __restrict__ W_in,
                            const float* __restrict__ W_h1,
                            const float* __restrict__ W_12,
                            const float* __restrict__ W_h2,
                            const float* __restrict__ W_out) {
    const int stride = gridDim.x * blockDim.x;
    const int g = blockIdx.x * blockDim.x + threadIdx.x;

    if (g < B * 4) ((int*)g_flag)[g] = 0;

    for (int d = g; d < DIN * H; d += stride) {
        int k = d >> 10, i = d & (H - 1);
        g_WT_in[d] = W_in[i * DIN + k];
    }
    for (int d = g; d < H * H; d += stride) {
        int j = d >> 10, i = d & (H - 1);
        g_WT_h1[d] = W_h1[i * H + j];
    }
    for (int d = g; d < H * H; d += stride) {
        int j = d >> 10, i = d & (H - 1);
        g_WT_12[d] = W_12[i * H + j];
    }
    for (int d = g; d < H * H; d += stride) {
        int j = d >> 10, i = d & (H - 1);
        g_WT_h2[d] = W_h2[i * H + j];
    }
    for (int d = g; d < H * DOUT; d += stride) {
        int j = d >> 8, o = d & (DOUT - 1);
        g_WT_out[d] = W_out[o * H + j];
    }
    // zero pad rows
    if (g < H) {
        g_WT_h1[H * H + g] = 0.0f;
        g_WT_12[H * H + g] = 0.0f;
        g_WT_h2[H * H + g] = 0.0f;
    }
    if (g < DOUT) g_WT_out[H * DOUT + g] = 0.0f;
}

// ---------------------------------------------------------------------------
// GEMM body (bit-exact vs R5): Xa tile = 128 rows x 64 cols.
// ---------------------------------------------------------------------------
#define GN H
#define GK DIN
#define BMT 128
#define BNT 64
#define BKT 16
#define NTILES (GN / BNT)   // 16

__device__ void gemm_body(const float* __restrict__ x,
                          const float* __restrict__ b_in, int gidx) {
    __shared__ float As[2][BKT][BMT + 4];
    __shared__ float Bs[2][BKT][BNT];

    const int bx = gidx & (NTILES - 1);
    const int byr = gidx >> 4;
    const int tb = byr >> 6;             // t-block 0..3 (t-block major)
    const int bb = byr & 63;             // batch
    const int bm = bb * T + tb * BMT;
    const int bn = bx * BNT;
    const int tid = threadIdx.x;
    const int tx = tid & 15;
    const int ty = tid >> 4;

    float acc[8][4];
#pragma unroll
    for (int i = 0; i < 8; ++i)
#pragma unroll
        for (int j = 0; j < 4; ++j) acc[i][j] = 0.0f;

    const int a_row0 = tid >> 2;
    const int a_kc = (tid & 3) * 4;
    const int b_k = tid >> 4;
    const int b_c = (tid & 15) * 4;

    const float* Aptr = x + (size_t)(bm + a_row0) * GK + a_kc;
    const float* Bptr = g_WT_in + (size_t)b_k * GN + bn + b_c;

    float4 pa0 = *(const float4*)(Aptr);
    float4 pa1 = *(const float4*)(Aptr + 64 * GK);
    float4 pb = *(const float4*)(Bptr);

    As[0][a_kc + 0][a_row0] = pa0.x;
    As[0][a_kc + 1][a_row0] = pa0.y;
    As[0][a_kc + 2][a_row0] = pa0.z;
    As[0][a_kc + 3][a_row0] = pa0.w;
    As[0][a_kc + 0][a_row0 + 64] = pa1.x;
    As[0][a_kc + 1][a_row0 + 64] = pa1.y;
    As[0][a_kc + 2][a_row0 + 64] = pa1.z;
    As[0][a_kc + 3][a_row0 + 64] = pa1.w;
    *(float4*)&Bs[0][b_k][b_c] = pb;
    __syncthreads();

    const int KT = GK / BKT;
    int buf = 0;
    for (int kt = 0; kt < KT; ++kt) {
        if (kt + 1 < KT) {
            const float* Ap = Aptr + (kt + 1) * BKT;
            pa0 = *(const float4*)(Ap);
            pa1 = *(const float4*)(Ap + 64 * GK);
            pb = *(const float4*)(Bptr + (size_t)(kt + 1) * BKT * GN);
        }
#pragma unroll
        for (int k = 0; k < BKT; ++k) {
            float4 a0 = *(const float4*)&As[buf][k][ty * 8];
            float4 a1 = *(const float4*)&As[buf][k][ty * 8 + 4];
            float4 bb2 = *(const float4*)&Bs[buf][k][tx * 4];
            float am[8] = {a0.x, a0.y, a0.z, a0.w, a1.x, a1.y, a1.z, a1.w};
            float bv[4] = {bb2.x, bb2.y, bb2.z, bb2.w};
#pragma unroll
            for (int i = 0; i < 8; ++i)
#pragma unroll
                for (int j = 0; j < 4; ++j)
                    acc[i][j] = fmaf(am[i], bv[j], acc[i][j]);
        }
        if (kt + 1 < KT) {
            const int nb = buf ^ 1;
            As[nb][a_kc + 0][a_row0] = pa0.x;
            As[nb][a_kc + 1][a_row0] = pa0.y;
            As[nb][a_kc + 2][a_row0] = pa0.z;
            As[nb][a_kc + 3][a_row0] = pa0.w;
            As[nb][a_kc + 0][a_row0 + 64] = pa1.x;
            As[nb][a_kc + 1][a_row0 + 64] = pa1.y;
            As[nb][a_kc + 2][a_row0 + 64] = pa1.z;
            As[nb][a_kc + 3][a_row0 + 64] = pa1.w;
            *(float4*)&Bs[nb][b_k][b_c] = pb;
        }
        buf ^= 1;
        __syncthreads();
    }

    float bias[4];
#pragma unroll
    for (int j = 0; j < 4; ++j) bias[j] = b_in[bn + tx * 4 + j];
#pragma unroll
    for (int i = 0; i < 8; ++i) {
        float4 o;
        o.x = acc[i][0] + bias[0];
        o.y = acc[i][1] + bias[1];
        o.z = acc[i][2] + bias[2];
        o.w = acc[i][3] + bias[3];
        *(float4*)&g_Xa[(size_t)(bm + ty * 8 + i) * GN + bn + tx * 4] = o;
    }

    __threadfence();
    __syncthreads();
    if (tid == 0) atomicAdd(&g_flag[bb][tb], 1);
}

// ---------------------------------------------------------------------------
// srnn: packed-f32 helpers + pipelined row accumulation
// ---------------------------------------------------------------------------
__device__ __forceinline__ unsigned long long addx2(unsigned long long a,
                                                    unsigned long long b) {
    unsigned long long r;
    asm("add.rn.f32x2 %0, %1, %2;" : "=l"(r) : "l"(a), "l"(b));
    return r;
}
__device__ __forceinline__ float lo2(unsigned long long v) {
    return __int_as_float((int)(unsigned)(v & 0xffffffffull));
}
__device__ __forceinline__ float hi2(unsigned long long v) {
    return __int_as_float((int)(unsigned)(v >> 32));
}

// load 8 weight rows (16B slices) using one LDS.128 for the 8 indices
__device__ __forceinline__ void ld_chunk(const float* __restrict__ wbase,
                                         const unsigned short* __restrict__ idx,
                                         int k, ulonglong2* buf) {
    uint4 iv = *(const uint4*)(idx + k);
    unsigned v;
    v = iv.x;
    buf[0] = *(const ulonglong2*)(wbase + ((v & 0xffffu) << 10));
    buf[1] = *(const ulonglong2*)(wbase + ((v >> 16) << 10));
    v = iv.y;
    buf[2] = *(const ulonglong2*)(wbase + ((v & 0xffffu) << 10));
    buf[3] = *(const ulonglong2*)(wbase + ((v >> 16) << 10));
    v = iv.z;
    buf[4] = *(const ulonglong2*)(wbase + ((v & 0xffffu) << 10));
    buf[5] = *(const ulonglong2*)(wbase + ((v >> 16) << 10));
    v = iv.w;
    buf[6] = *(const ulonglong2*)(wbase + ((v & 0xffffu) << 10));
    buf[7] = *(const ulonglong2*)(wbase + ((v >> 16) << 10));
}

__device__ __forceinline__ void acc_chunk(const ulonglong2* buf,
                                          unsigned long long& a01,
                                          unsigned long long& a23) {
#pragma unroll
    for (int j = 0; j < 8; ++j) {
        a01 = addx2(a01, buf[j].x);
        a23 = addx2(a23, buf[j].y);
    }
}

// n is a multiple of 16 (possibly 0). Accumulation order identical to the
// plain ascending loop: chunk 0..nc-1, ascending j within each chunk.
__device__ __forceinline__ void accum_rows(const float* __restrict__ wbase,
                                           const unsigned short* __restrict__ idx,
                                           int n, unsigned long long& a01,
                                           unsigned long long& a23) {
    const int nc = n >> 4;     // number of 16-row pairs
    if (nc == 0) return;
    ulonglong2 A[8], Bf[8];
    ld_chunk(wbase, idx, 0, A);
    ld_chunk(wbase, idx, 8, Bf);
    int k = 16;
    for (int c = 1; c < nc; ++c) {
        acc_chunk(A, a01, a23);
        ld_chunk(wbase, idx, k, A);
        acc_chunk(Bf, a01, a23);
        ld_chunk(wbase, idx, k + 8, Bf);
        k += 16;
    }
    acc_chunk(A, a01, a23);
    acc_chunk(Bf, a01, a23);
}

__device__ void srnn_body(const float* __restrict__ b_h1,
                          const float* __restrict__ b_12,
                          const float* __restrict__ b_h2,
                          const float* __restrict__ b_out,
                          float* __restrict__ out) {
    const int b = blockIdx.x;
    const int tid = threadIdx.x;
    const int lane = tid & 31;

    __shared__ alignas(16) unsigned short idx1[H + 16];
    __shared__ alignas(16) unsigned short idx2[H + 16];
    __shared__ unsigned int nibs[256];
    __shared__ int cnt_s;
    __shared__ float4 red4[256];

    const int col = tid * 4;
    const float* wh1 = g_WT_h1 + col;
    const float* w12 = g_WT_12 + col;
    const float* wh2 = g_WT_h2 + col;

    float4 v1 = make_float4(0.f, 0.f, 0.f, 0.f);
    float4 v2 = make_float4(0.f, 0.f, 0.f, 0.f);

    const float4 bh1 = *(const float4*)(b_h1 + col);
    const float4 b12 = *(const float4*)(b_12 + col);
    const float4 bh2 = *(const float4*)(b_h2 + col);

    const int r = tid >> 6;
    const int o = tid & 63;
    const float* wout = g_WT_out + o * 4;
    float4 accp = make_float4(0.f, 0.f, 0.f, 0.f);
    float4 bo = make_float4(0.f, 0.f, 0.f, 0.f);
    if (r == 0) bo = *(const float4*)(b_out + o * 4);

    const float* Xb = g_Xa + (size_t)b * T * H;

    int n1 = 0, n2 = 0;   // padded (multiple-of-16) spike counts

    for (int t = 0; t < T; ++t) {
        if ((t & 127) == 0) {          // acquire next 128-step block of Xa
            const int tb = t >> 7;
            if (tid == 0) {
                while (atomicAdd(&g_flag[b][tb], 0) < NTILES) __nanosleep(200);
            }
            __syncthreads();
            __threadfence();
        }

        // ================= layer 1 =================
        float4 hx = *(const float4*)(Xb + t * H + col);   // xW + b_in
        unsigned long long r01 = 0ull, r23 = 0ull;
        accum_rows(wh1, idx1, n1, r01, r23);
        float n0 = (hx.x + lo2(r01)) + bh1.x;
        float nn1 = (hx.y + hi2(r01)) + bh1.y;
        float nn2 = (hx.z + lo2(r23)) + bh1.z;
        float n3 = (hx.w + hi2(r23)) + bh1.w;
        v1.x = fmaf(BETA, v1.x, n0);
        v1.y = fmaf(BETA, v1.y, nn1);
        v1.z = fmaf(BETA, v1.z, nn2);
        v1.w = fmaf(BETA, v1.w, n3);
        bool s0 = v1.x >= THRESH;
        bool s1 = v1.y >= THRESH;
        bool s2 = v1.z >= THRESH;
        bool s3 = v1.w >= THRESH;
        if (s0) v1.x -= THRESH;
        if (s1) v1.y -= THRESH;
        if (s2) v1.z -= THRESH;
        if (s3) v1.w -= THRESH;
        nibs[tid] = (unsigned)s0 | ((unsigned)s1 << 1) | ((unsigned)s2 << 2) |
                    ((unsigned)s3 << 3);
        __syncthreads();
        if (tid < 32) {   // compact (ascending) + pad to multiple of 16
            const unsigned int* nb = &nibs[tid * 8];
            unsigned m = 0;
#pragma unroll
            for (int i = 0; i < 8; ++i) m |= nb[i] << (i * 4);
            int p = __popc(m);
            int off = p;
#pragma unroll
            for (int s = 1; s < 32; s <<= 1) {
                int n = __shfl_up_sync(0xffffffffu, off, s);
                if (lane >= s) off += n;
            }
            int tot = __shfl_sync(0xffffffffu, off, 31);
            if (tid == 31) cnt_s = (tot + 15) & ~15;
            off -= p;
            const int base = tid * 32;
            while (m) {
                int bit = __ffs(m) - 1;
                m &= m - 1;
                idx1[off++] = (unsigned short)(base + bit);
            }
            int npad = ((tot + 15) & ~15) - tot;
            if (tid < npad) idx1[tot + tid] = (unsigned short)ZROW;
        }
        __syncthreads();
        n1 = cnt_s;

        // ================= layer 2 =================
        unsigned long long a01 = 0ull, a23 = 0ull;
        accum_rows(w12, idx1, n1, a01, a23);
        unsigned long long c01 = 0ull, c23 = 0ull;
        accum_rows(wh2, idx2, n2, c01, c23);
        __syncthreads();   // idx2 about to be overwritten
        float m0 = ((lo2(a01) + b12.x) + lo2(c01)) + bh2.x;
        float m1 = ((hi2(a01) + b12.y) + hi2(c01)) + bh2.y;
        float m2 = ((lo2(a23) + b12.z) + lo2(c23)) + bh2.z;
        float m3 = ((hi2(a23) + b12.w) + hi2(c23)) + bh2.w;
        v2.x = fmaf(BETA, v2.x, m0);
        v2.y = fmaf(BETA, v2.y, m1);
        v2.z = fmaf(BETA, v2.z, m2);
        v2.w = fmaf(BETA, v2.w, m3);
        s0 = v2.x >= THRESH;
        s1 = v2.y >= THRESH;
        s2 = v2.z >= THRESH;
        s3 = v2.w >= THRESH;
        if (s0) v2.x -= THRESH;
        if (s1) v2.y -= THRESH;
        if (s2) v2.z -= THRESH;
        if (s3) v2.w -= THRESH;
        nibs[tid] = (unsigned)s0 | ((unsigned)s1 << 1) | ((unsigned)s2 << 2) |
                    ((unsigned)s3 << 3);
        __syncthreads();
        if (tid < 32) {
            const unsigned int* nb = &nibs[tid * 8];
            unsigned m = 0;
#pragma unroll
            for (int i = 0; i < 8; ++i) m |= nb[i] << (i * 4);
            int p = __popc(m);
            int off = p;
#pragma unroll
            for (int s = 1; s < 32; s <<= 1) {
                int n = __shfl_up_sync(0xffffffffu, off, s);
                if (lane >= s) off += n;
            }
            int tot = __shfl_sync(0xffffffffu, off, 31);
            if (tid == 31) cnt_s = (tot + 15) & ~15;
            off -= p;
            const int base = tid * 32;
            while (m) {
                int bit = __ffs(m) - 1;
                m &= m - 1;
                idx2[off++] = (unsigned short)(base + bit);
            }
            int npad = ((tot + 15) & ~15) - tot;
            if (tid < npad) idx2[tot + tid] = (unsigned short)ZROW;
        }
        __syncthreads();
        n2 = cnt_s;

        // ================= readout acc (4-deep buffered; pads add +0) ======
        {
            float4 a = accp;
            if (r == 0) {
                a.x += bo.x;
                a.y += bo.y;
                a.z += bo.z;
                a.w += bo.w;
            }
            for (int k = r; k < n2; k += 16) {
                float4 w0 = *(const float4*)(wout + ((int)idx2[k] << 8));
                float4 w1 = *(const float4*)(wout + ((int)idx2[k + 4] << 8));
                float4 w2 = *(const float4*)(wout + ((int)idx2[k + 8] << 8));
                float4 w3 = *(const float4*)(wout + ((int)idx2[k + 12] << 8));
                a.x += w0.x; a.y += w0.y; a.z += w0.z; a.w += w0.w;
                a.x += w1.x; a.y += w1.y; a.z += w1.z; a.w += w1.w;
                a.x += w2.x; a.y += w2.y; a.z += w2.z; a.w += w2.w;
                a.x += w3.x; a.y += w3.y; a.z += w3.z; a.w += w3.w;
            }
            accp = a;
        }
    }

    red4[tid] = accp;
    __syncthreads();
    if (tid < 64) {
        float4 s = red4[tid];
        float4 p1 = red4[tid + 64];
        float4 p2 = red4[tid + 128];
        float4 p3 = red4[tid + 192];
        s.x += p1.x; s.y += p1.y; s.z += p1.z; s.w += p1.w;
        s.x += p2.x; s.y += p2.y; s.z += p2.z; s.w += p2.w;
        s.x += p3.x; s.y += p3.y; s.z += p3.z; s.w += p3.w;
        *(float4*)&out[b * DOUT + tid * 4] = s;
    }
}

// ---------------------------------------------------------------------------
// Fused producer/consumer kernel.
// ---------------------------------------------------------------------------
__global__ __launch_bounds__(256) void fused_kernel(
    const float* __restrict__ x, const float* __restrict__ b_in,
    const float* __restrict__ b_h1, const float* __restrict__ b_12,
    const float* __restrict__ b_h2, const float* __restrict__ b_out,
    float* __restrict__ out) {
    if (blockIdx.x < B) {
        srnn_body(b_h1, b_12, b_h2, b_out, out);
    } else {
        gemm_body(x, b_in, blockIdx.x - B);
    }
}

// ---------------------------------------------------------------------------
// kernel_launch
// Inputs: 0 x, 1 W_in, 2 b_in, 3 W_h1, 4 b_h1, 5 W_12, 6 b_12, 7 W_h2,
//         8 b_h2, 9 W_out, 10 b_out
// ---------------------------------------------------------------------------
extern "C" void kernel_launch(void* const* d_in, const int* in_sizes, int n_in,
                              void* d_out, int out_size) {
    const float* x = (const float*)d_in[0];
    const float* W_in = (const float*)d_in[1];
    const float* b_in = (const float*)d_in[2];
    const float* W_h1 = (const float*)d_in[3];
    const float* b_h1 = (const float*)d_in[4];
    const float* W_12 = (const float*)d_in[5];
    const float* b_12 = (const float*)d_in[6];
    const float* W_h2 = (const float*)d_in[7];
    const float* b_h2 = (const float*)d_in[8];
    const float* W_out = (const float*)d_in[9];
    const float* b_out = (const float*)d_in[10];
    float* out = (float*)d_out;

    prep_kernel<<<1024, 256>>>(W_in, W_h1, W_12, W_h2, W_out);
    const int total_tiles = (B * T / BMT) * NTILES;   // 4096
    fused_kernel<<<B + total_tiles, 256>>>(x, b_in, b_h1, b_12, b_h2, b_out, out);
}

// round 13
// speedup vs baseline: 1.6898x; 1.0046x over previous
#include <cuda_runtime.h>
#include <cstdint>

// ---------------------------------------------------------------------------
// SimpleSRNN: 2-layer LIF spiking RNN, B=64, T=512, D_IN=512, H1=H2=1024,
// D_OUT=256.
//   K0: transpose weights (+ zero pad-row) + zero progress flags
//   K_fused: CTAs 0..63 = persistent per-batch recurrent consumers,
//            CTAs 64..4159 = SGEMM producer tiles (Xa = x@W_in.T + b_in).
//   R7 -> R8: spike-row accumulation is software-pipelined with 2x8-row
//   register buffers (MLP ~16 vs ~4). Index lists padded to multiples of 16
//   with a ZERO weight row (exact: x + 0.0 == x), preserving the bit-exact
//   accumulation order of the passing kernel.
// ---------------------------------------------------------------------------

#define BETA 0.9f
#define THRESH 1.0f

static constexpr int B = 64;
static constexpr int T = 512;
static constexpr int DIN = 512;
static constexpr int H = 1024;      // H1 == H2
static constexpr int DOUT = 256;
static constexpr int ZROW = H;      // index of the all-zero pad row

// ---- device scratch (static allocation only) ------------------------------
__device__ float g_Xa[(size_t)B * T * H];          // x@W_in.T + b_in (128 MB)
__device__ float g_WT_h1[H * H + H];               // [j][i], + zero row
__device__ float g_WT_12[H * H + H];
__device__ float g_WT_h2[H * H + H];
__device__ float g_WT_in[DIN * H];                 // [k][i]
__device__ float g_WT_out[H * DOUT + DOUT];        // [j][o], + zero row
__device__ int   g_flag[B][4];                     // tiles done per (b, tblock)

// ---------------------------------------------------------------------------
// K0: weight transposes + zero rows + flag reset
// ---------------------------------------------------------------------------
__global__ void prep_kernel(const float* __restrict__ W_in,
                            const float* __restrict__ W_h1,
                            const float* __restrict__ W_12,
                            const float* __restrict__ W_h2,
                            const float* __restrict__ W_out) {
    const int stride = gridDim.x * blockDim.x;
    const int g = blockIdx.x * blockDim.x + threadIdx.x;

    if (g < B * 4) ((int*)g_flag)[g] = 0;

    for (int d = g; d < DIN * H; d += stride) {
        int k = d >> 10, i = d & (H - 1);
        g_WT_in[d] = W_in[i * DIN + k];
    }
    for (int d = g; d < H * H; d += stride) {
        int j = d >> 10, i = d & (H - 1);
        g_WT_h1[d] = W_h1[i * H + j];
    }
    for (int d = g; d < H * H; d += stride) {
        int j = d >> 10, i = d & (H - 1);
        g_WT_12[d] = W_12[i * H + j];
    }
    for (int d = g; d < H * H; d += stride) {
        int j = d >> 10, i = d & (H - 1);
        g_WT_h2[d] = W_h2[i * H + j];
    }
    for (int d = g; d < H * DOUT; d += stride) {
        int j = d >> 8, o = d & (DOUT - 1);
        g_WT_out[d] = W_out[o * H + j];
    }
    // zero pad rows
    if (g < H) {
        g_WT_h1[H * H + g] = 0.0f;
        g_WT_12[H * H + g] = 0.0f;
        g_WT_h2[H * H + g] = 0.0f;
    }
    if (g < DOUT) g_WT_out[H * DOUT + g] = 0.0f;
}

// ---------------------------------------------------------------------------
// GEMM body (bit-exact vs R5): Xa tile = 128 rows x 64 cols.
// ---------------------------------------------------------------------------
#define GN H
#define GK DIN
#define BMT 128
#define BNT 64
#define BKT 16
#define NTILES (GN / BNT)   // 16

__device__ void gemm_body(const float* __restrict__ x,
                          const float* __restrict__ b_in, int gidx) {
    __shared__ float As[2][BKT][BMT + 4];
    __shared__ float Bs[2][BKT][BNT];

    const int bx = gidx & (NTILES - 1);
    const int byr = gidx >> 4;
    const int tb = byr >> 6;             // t-block 0..3 (t-block major)
    const int bb = byr & 63;             // batch
    const int bm = bb * T + tb * BMT;
    const int bn = bx * BNT;
    const int tid = threadIdx.x;
    const int tx = tid & 15;
    const int ty = tid >> 4;

    float acc[8][4];
#pragma unroll
    for (int i = 0; i < 8; ++i)
#pragma unroll
        for (int j = 0; j < 4; ++j) acc[i][j] = 0.0f;

    const int a_row0 = tid >> 2;
    const int a_kc = (tid & 3) * 4;
    const int b_k = tid >> 4;
    const int b_c = (tid & 15) * 4;

    const float* Aptr = x + (size_t)(bm + a_row0) * GK + a_kc;
    const float* Bptr = g_WT_in + (size_t)b_k * GN + bn + b_c;

    float4 pa0 = *(const float4*)(Aptr);
    float4 pa1 = *(const float4*)(Aptr + 64 * GK);
    float4 pb = *(const float4*)(Bptr);

    As[0][a_kc + 0][a_row0] = pa0.x;
    As[0][a_kc + 1][a_row0] = pa0.y;
    As[0][a_kc + 2][a_row0] = pa0.z;
    As[0][a_kc + 3][a_row0] = pa0.w;
    As[0][a_kc + 0][a_row0 + 64] = pa1.x;
    As[0][a_kc + 1][a_row0 + 64] = pa1.y;
    As[0][a_kc + 2][a_row0 + 64] = pa1.z;
    As[0][a_kc + 3][a_row0 + 64] = pa1.w;
    *(float4*)&Bs[0][b_k][b_c] = pb;
    __syncthreads();

    const int KT = GK / BKT;
    int buf = 0;
    for (int kt = 0; kt < KT; ++kt) {
        if (kt + 1 < KT) {
            const float* Ap = Aptr + (kt + 1) * BKT;
            pa0 = *(const float4*)(Ap);
            pa1 = *(const float4*)(Ap + 64 * GK);
            pb = *(const float4*)(Bptr + (size_t)(kt + 1) * BKT * GN);
        }
#pragma unroll
        for (int k = 0; k < BKT; ++k) {
            float4 a0 = *(const float4*)&As[buf][k][ty * 8];
            float4 a1 = *(const float4*)&As[buf][k][ty * 8 + 4];
            float4 bb2 = *(const float4*)&Bs[buf][k][tx * 4];
            float am[8] = {a0.x, a0.y, a0.z, a0.w, a1.x, a1.y, a1.z, a1.w};
            float bv[4] = {bb2.x, bb2.y, bb2.z, bb2.w};
#pragma unroll
            for (int i = 0; i < 8; ++i)
#pragma unroll
                for (int j = 0; j < 4; ++j)
                    acc[i][j] = fmaf(am[i], bv[j], acc[i][j]);
        }
        if (kt + 1 < KT) {
            const int nb = buf ^ 1;
            As[nb][a_kc + 0][a_row0] = pa0.x;
            As[nb][a_kc + 1][a_row0] = pa0.y;
            As[nb][a_kc + 2][a_row0] = pa0.z;
            As[nb][a_kc + 3][a_row0] = pa0.w;
            As[nb][a_kc + 0][a_row0 + 64] = pa1.x;
            As[nb][a_kc + 1][a_row0 + 64] = pa1.y;
            As[nb][a_kc + 2][a_row0 + 64] = pa1.z;
            As[nb][a_kc + 3][a_row0 + 64] = pa1.w;
            *(float4*)&Bs[nb][b_k][b_c] = pb;
        }
        buf ^= 1;
        __syncthreads();
    }

    float bias[4];
#pragma unroll
    for (int j = 0; j < 4; ++j) bias[j] = b_in[bn + tx * 4 + j];
#pragma unroll
    for (int i = 0; i < 8; ++i) {
        float4 o;
        o.x = acc[i][0] + bias[0];
        o.y = acc[i][1] + bias[1];
        o.z = acc[i][2] + bias[2];
        o.w = acc[i][3] + bias[3];
        *(float4*)&g_Xa[(size_t)(bm + ty * 8 + i) * GN + bn + tx * 4] = o;
    }

    __threadfence();
    __syncthreads();
    if (tid == 0) atomicAdd(&g_flag[bb][tb], 1);
}

// ---------------------------------------------------------------------------
// srnn: packed-f32 helpers + pipelined row accumulation
// ---------------------------------------------------------------------------
__device__ __forceinline__ unsigned long long addx2(unsigned long long a,
                                                    unsigned long long b) {
    unsigned long long r;
    asm("add.rn.f32x2 %0, %1, %2;" : "=l"(r) : "l"(a), "l"(b));
    return r;
}
__device__ __forceinline__ float lo2(unsigned long long v) {
    return __int_as_float((int)(unsigned)(v & 0xffffffffull));
}
__device__ __forceinline__ float hi2(unsigned long long v) {
    return __int_as_float((int)(unsigned)(v >> 32));
}

// load 8 weight rows (16B slices) using one LDS.128 for the 8 indices
__device__ __forceinline__ void ld_chunk(const float* __restrict__ wbase,
                                         const unsigned short* __restrict__ idx,
                                         int k, ulonglong2* buf) {
    uint4 iv = *(const uint4*)(idx + k);
    unsigned v;
    v = iv.x;
    buf[0] = *(const ulonglong2*)(wbase + ((v & 0xffffu) << 10));
    buf[1] = *(const ulonglong2*)(wbase + ((v >> 16) << 10));
    v = iv.y;
    buf[2] = *(const ulonglong2*)(wbase + ((v & 0xffffu) << 10));
    buf[3] = *(const ulonglong2*)(wbase + ((v >> 16) << 10));
    v = iv.z;
    buf[4] = *(const ulonglong2*)(wbase + ((v & 0xffffu) << 10));
    buf[5] = *(const ulonglong2*)(wbase + ((v >> 16) << 10));
    v = iv.w;
    buf[6] = *(const ulonglong2*)(wbase + ((v & 0xffffu) << 10));
    buf[7] = *(const ulonglong2*)(wbase + ((v >> 16) << 10));
}

__device__ __forceinline__ void acc_chunk(const ulonglong2* buf,
                                          unsigned long long& a01,
                                          unsigned long long& a23) {
#pragma unroll
    for (int j = 0; j < 8; ++j) {
        a01 = addx2(a01, buf[j].x);
        a23 = addx2(a23, buf[j].y);
    }
}

// n is a multiple of 16 (possibly 0). Accumulation order identical to the
// plain ascending loop: chunk 0..nc-1, ascending j within each chunk.
__device__ __forceinline__ void accum_rows(const float* __restrict__ wbase,
                                           const unsigned short* __restrict__ idx,
                                           int n, unsigned long long& a01,
                                           unsigned long long& a23) {
    const int nc = n >> 4;     // number of 16-row pairs
    if (nc == 0) return;
    ulonglong2 A[8], Bf[8];
    ld_chunk(wbase, idx, 0, A);
    ld_chunk(wbase, idx, 8, Bf);
    int k = 16;
    for (int c = 1; c < nc; ++c) {
        acc_chunk(A, a01, a23);
        ld_chunk(wbase, idx, k, A);
        acc_chunk(Bf, a01, a23);
        ld_chunk(wbase, idx, k + 8, Bf);
        k += 16;
    }
    acc_chunk(A, a01, a23);
    acc_chunk(Bf, a01, a23);
}

__device__ void srnn_body(const float* __restrict__ b_h1,
                          const float* __restrict__ b_12,
                          const float* __restrict__ b_h2,
                          const float* __restrict__ b_out,
                          float* __restrict__ out) {
    const int b = blockIdx.x;
    const int tid = threadIdx.x;
    const int lane = tid & 31;

    __shared__ alignas(16) unsigned short idx1[H + 16];
    __shared__ alignas(16) unsigned short idx2[H + 16];
    __shared__ unsigned int nibs[256];
    __shared__ int cnt_s;
    __shared__ float4 red4[256];

    const int col = tid * 4;
    const float* wh1 = g_WT_h1 + col;
    const float* w12 = g_WT_12 + col;
    const float* wh2 = g_WT_h2 + col;

    float4 v1 = make_float4(0.f, 0.f, 0.f, 0.f);
    float4 v2 = make_float4(0.f, 0.f, 0.f, 0.f);

    const float4 bh1 = *(const float4*)(b_h1 + col);
    const float4 b12 = *(const float4*)(b_12 + col);
    const float4 bh2 = *(const float4*)(b_h2 + col);

    const int r = tid >> 6;
    const int o = tid & 63;
    const float* wout = g_WT_out + o * 4;
    float4 accp = make_float4(0.f, 0.f, 0.f, 0.f);
    float4 bo = make_float4(0.f, 0.f, 0.f, 0.f);
    if (r == 0) bo = *(const float4*)(b_out + o * 4);

    const float* Xb = g_Xa + (size_t)b * T * H;

    int n1 = 0, n2 = 0;   // padded (multiple-of-16) spike counts

    for (int t = 0; t < T; ++t) {
        if ((t & 127) == 0) {          // acquire next 128-step block of Xa
            const int tb = t >> 7;
            if (tid == 0) {
                while (atomicAdd(&g_flag[b][tb], 0) < NTILES) __nanosleep(200);
            }
            __syncthreads();
            __threadfence();
        }

        // ================= layer 1 =================
        float4 hx = *(const float4*)(Xb + t * H + col);   // xW + b_in
        unsigned long long r01 = 0ull, r23 = 0ull;
        accum_rows(wh1, idx1, n1, r01, r23);
        float n0 = (hx.x + lo2(r01)) + bh1.x;
        float nn1 = (hx.y + hi2(r01)) + bh1.y;
        float nn2 = (hx.z + lo2(r23)) + bh1.z;
        float n3 = (hx.w + hi2(r23)) + bh1.w;
        v1.x = fmaf(BETA, v1.x, n0);
        v1.y = fmaf(BETA, v1.y, nn1);
        v1.z = fmaf(BETA, v1.z, nn2);
        v1.w = fmaf(BETA, v1.w, n3);
        bool s0 = v1.x >= THRESH;
        bool s1 = v1.y >= THRESH;
        bool s2 = v1.z >= THRESH;
        bool s3 = v1.w >= THRESH;
        if (s0) v1.x -= THRESH;
        if (s1) v1.y -= THRESH;
        if (s2) v1.z -= THRESH;
        if (s3) v1.w -= THRESH;
        nibs[tid] = (unsigned)s0 | ((unsigned)s1 << 1) | ((unsigned)s2 << 2) |
                    ((unsigned)s3 << 3);
        __syncthreads();
        if (tid < 32) {   // compact (ascending) + pad to multiple of 16
            const unsigned int* nb = &nibs[tid * 8];
            unsigned m = 0;
#pragma unroll
            for (int i = 0; i < 8; ++i) m |= nb[i] << (i * 4);
            int p = __popc(m);
            int off = p;
#pragma unroll
            for (int s = 1; s < 32; s <<= 1) {
                int n = __shfl_up_sync(0xffffffffu, off, s);
                if (lane >= s) off += n;
            }
            int tot = __shfl_sync(0xffffffffu, off, 31);
            if (tid == 31) cnt_s = (tot + 15) & ~15;
            off -= p;
            const int base = tid * 32;
            while (m) {
                int bit = __ffs(m) - 1;
                m &= m - 1;
                idx1[off++] = (unsigned short)(base + bit);
            }
            int npad = ((tot + 15) & ~15) - tot;
            if (tid < npad) idx1[tot + tid] = (unsigned short)ZROW;
        }
        __syncthreads();
        n1 = cnt_s;

        // ================= layer 2 =================
        unsigned long long a01 = 0ull, a23 = 0ull;
        accum_rows(w12, idx1, n1, a01, a23);
        unsigned long long c01 = 0ull, c23 = 0ull;
        accum_rows(wh2, idx2, n2, c01, c23);
        __syncthreads();   // idx2 about to be overwritten
        float m0 = ((lo2(a01) + b12.x) + lo2(c01)) + bh2.x;
        float m1 = ((hi2(a01) + b12.y) + hi2(c01)) + bh2.y;
        float m2 = ((lo2(a23) + b12.z) + lo2(c23)) + bh2.z;
        float m3 = ((hi2(a23) + b12.w) + hi2(c23)) + bh2.w;
        v2.x = fmaf(BETA, v2.x, m0);
        v2.y = fmaf(BETA, v2.y, m1);
        v2.z = fmaf(BETA, v2.z, m2);
        v2.w = fmaf(BETA, v2.w, m3);
        s0 = v2.x >= THRESH;
        s1 = v2.y >= THRESH;
        s2 = v2.z >= THRESH;
        s3 = v2.w >= THRESH;
        if (s0) v2.x -= THRESH;
        if (s1) v2.y -= THRESH;
        if (s2) v2.z -= THRESH;
        if (s3) v2.w -= THRESH;
        nibs[tid] = (unsigned)s0 | ((unsigned)s1 << 1) | ((unsigned)s2 << 2) |
                    ((unsigned)s3 << 3);
        __syncthreads();
        if (tid < 32) {
            const unsigned int* nb = &nibs[tid * 8];
            unsigned m = 0;
#pragma unroll
            for (int i = 0; i < 8; ++i) m |= nb[i] << (i * 4);
            int p = __popc(m);
            int off = p;
#pragma unroll
            for (int s = 1; s < 32; s <<= 1) {
                int n = __shfl_up_sync(0xffffffffu, off, s);
                if (lane >= s) off += n;
            }
            int tot = __shfl_sync(0xffffffffu, off, 31);
            if (tid == 31) cnt_s = (tot + 15) & ~15;
            off -= p;
            const int base = tid * 32;
            while (m) {
                int bit = __ffs(m) - 1;
                m &= m - 1;
                idx2[off++] = (unsigned short)(base + bit);
            }
            int npad = ((tot + 15) & ~15) - tot;
            if (tid < npad) idx2[tot + tid] = (unsigned short)ZROW;
        }
        __syncthreads();
        n2 = cnt_s;

        // ================= readout acc (4-deep buffered; pads add +0) ======
        {
            float4 a = accp;
            if (r == 0) {
                a.x += bo.x;
                a.y += bo.y;
                a.z += bo.z;
                a.w += bo.w;
            }
            for (int k = r; k < n2; k += 16) {
                float4 w0 = *(const float4*)(wout + ((int)idx2[k] << 8));
                float4 w1 = *(const float4*)(wout + ((int)idx2[k + 4] << 8));
                float4 w2 = *(const float4*)(wout + ((int)idx2[k + 8] << 8));
                float4 w3 = *(const float4*)(wout + ((int)idx2[k + 12] << 8));
                a.x += w0.x; a.y += w0.y; a.z += w0.z; a.w += w0.w;
                a.x += w1.x; a.y += w1.y; a.z += w1.z; a.w += w1.w;
                a.x += w2.x; a.y += w2.y; a.z += w2.z; a.w += w2.w;
                a.x += w3.x; a.y += w3.y; a.z += w3.z; a.w += w3.w;
            }
            accp = a;
        }
    }

    red4[tid] = accp;
    __syncthreads();
    if (tid < 64) {
        float4 s = red4[tid];
        float4 p1 = red4[tid + 64];
        float4 p2 = red4[tid + 128];
        float4 p3 = red4[tid + 192];
        s.x += p1.x; s.y += p1.y; s.z += p1.z; s.w += p1.w;
        s.x += p2.x; s.y += p2.y; s.z += p2.z; s.w += p2.w;
        s.x += p3.x; s.y += p3.y; s.z += p3.z; s.w += p3.w;
        *(float4*)&out[b * DOUT + tid * 4] = s;
    }
}

// ---------------------------------------------------------------------------
// Fused producer/consumer kernel.
// ---------------------------------------------------------------------------
__global__ __launch_bounds__(256) void fused_kernel(
    const float* __restrict__ x, const float* __restrict__ b_in,
    const float* __restrict__ b_h1, const float* __restrict__ b_12,
    const float* __restrict__ b_h2, const float* __restrict__ b_out,
    float* __restrict__ out) {
    if (blockIdx.x < B) {
        srnn_body(b_h1, b_12, b_h2, b_out, out);
    } else {
        gemm_body(x, b_in, blockIdx.x - B);
    }
}

// ---------------------------------------------------------------------------
// kernel_launch
// Inputs: 0 x, 1 W_in, 2 b_in, 3 W_h1, 4 b_h1, 5 W_12, 6 b_12, 7 W_h2,
//         8 b_h2, 9 W_out, 10 b_out
// ---------------------------------------------------------------------------
extern "C" void kernel_launch(void* const* d_in, const int* in_sizes, int n_in,
                              void* d_out, int out_size) {
    const float* x = (const float*)d_in[0];
    const float* W_in = (const float*)d_in[1];
    const float* b_in = (const float*)d_in[2];
    const float* W_h1 = (const float*)d_in[3];
    const float* b_h1 = (const float*)d_in[4];
    const float* W_12 = (const float*)d_in[5];
    const float* b_12 = (const float*)d_in[6];
    const float* W_h2 = (const float*)d_in[7];
    const float* b_h2 = (const float*)d_in[8];
    const float* W_out = (const float*)d_in[9];
    const float* b_out = (const float*)d_in[10];
    float* out = (float*)d_out;

    prep_kernel<<<1024, 256>>>(W_in, W_h1, W_12, W_h2, W_out);
    const int total_tiles = (B * T / BMT) * NTILES;   // 4096
    fused_kernel<<<B + total_tiles, 256>>>(x, b_in, b_h1, b_12, b_h2, b_out, out);
}